// round 1
// baseline (speedup 1.0000x reference)
#include <cuda_runtime.h>
#include <cstddef>

#define EPS_BN 1e-5f

// Problem constants (fixed shapes from reference setup_inputs)
constexpr int Bb = 4;
constexpr int Cc = 2048;
constexpr int Rr = 512;
constexpr int Nn = 4096;          // H*W = 64*64

// Scratch (allocation-free: __device__ globals)
__device__ float g_F[(size_t)Bb * Rr * Nn];   // 33.5 MB
__device__ float g_Q[(size_t)Bb * Rr * Nn];
__device__ float g_K[(size_t)Bb * Rr * Nn];
__device__ float g_V[(size_t)Bb * Rr * Nn];
__device__ float g_U[(size_t)Bb * Rr * Nn];
__device__ float g_S[(size_t)Bb * Nn * Nn];   // 268 MB attention logits/probs
__device__ float g_alpha[5 * 2048];
__device__ float g_beta[5 * 2048];

// ---------------------------------------------------------------------------
// BN folding: alpha = g*rsqrt(v+eps); beta = b - m*alpha
// ---------------------------------------------------------------------------
__global__ void prep_kernel(const float* __restrict__ g, const float* __restrict__ b,
                            const float* __restrict__ m, const float* __restrict__ v,
                            float* __restrict__ al, float* __restrict__ be, int n) {
    int i = blockIdx.x * blockDim.x + threadIdx.x;
    if (i < n) {
        float a = g[i] * rsqrtf(v[i] + EPS_BN);
        al[i] = a;
        be[i] = b[i] - m[i] * a;
    }
}

// ---------------------------------------------------------------------------
// Generic tiled SGEMM: C[i,j] = sum_k Aop[i,k]*Bop[k,j]
//   TA=false: Aop[i,k]=A[i*lda+k]   TA=true: Aop[i,k]=A[k*lda+i]
//   TB=false: Bop[k,j]=B[k*ldb+j]   TB=true: Bop[k,j]=B[j*ldb+k]
// RELU_SB: C = relu(alpha[i]*acc + beta[i])
// BM=BN=64, BK=16, 256 threads, 4x4 per thread. All dims multiples of tiles.
// ---------------------------------------------------------------------------
template <bool TA, bool TB, bool RELU_SB>
__global__ void __launch_bounds__(256, 2) sgemm_kernel(
    const float* __restrict__ A, const float* __restrict__ Bm,
    float* __restrict__ Cm, int K, int lda, int ldb, int ldc,
    long sA, long sB, long sC,
    const float* __restrict__ alpha, const float* __restrict__ beta) {
    constexpr int BK = 16;
    constexpr int LDSH = 68;  // padded row stride (keeps 16B alignment, reduces conflicts)
    __shared__ float As[BK * LDSH];
    __shared__ float Bs[BK * LDSH];

    const int t = threadIdx.x;
    const int tx = t & 15;
    const int ty = t >> 4;
    const int bi = blockIdx.y * 64;  // row tile
    const int bj = blockIdx.x * 64;  // col tile
    const int bz = blockIdx.z;
    A += sA * bz;
    Bm += sB * bz;
    Cm += sC * bz;

    float acc[4][4] = {};

    for (int k0 = 0; k0 < K; k0 += BK) {
        // ---- load A tile -> As[k][i] ----
        if (!TA) {
            // A row-major, contiguous along k: float4 along k, scatter into shared
            int i = t >> 2;
            int kk = (t & 3) * 4;
            float4 v = *reinterpret_cast<const float4*>(
                &A[(size_t)(bi + i) * lda + k0 + kk]);
            As[(kk + 0) * LDSH + i] = v.x;
            As[(kk + 1) * LDSH + i] = v.y;
            As[(kk + 2) * LDSH + i] = v.z;
            As[(kk + 3) * LDSH + i] = v.w;
        } else {
            // contiguous along i: float4 along i
            int i4 = (t & 15) * 4;
            int kk = t >> 4;
            float4 v = *reinterpret_cast<const float4*>(
                &A[(size_t)(k0 + kk) * lda + bi + i4]);
            *reinterpret_cast<float4*>(&As[kk * LDSH + i4]) = v;
        }
        // ---- load B tile -> Bs[k][j] ----
        if (!TB) {
            int j4 = (t & 15) * 4;
            int kk = t >> 4;
            float4 v = *reinterpret_cast<const float4*>(
                &Bm[(size_t)(k0 + kk) * ldb + bj + j4]);
            *reinterpret_cast<float4*>(&Bs[kk * LDSH + j4]) = v;
        } else {
            int j = t >> 2;
            int kk = (t & 3) * 4;
            float4 v = *reinterpret_cast<const float4*>(
                &Bm[(size_t)(bj + j) * ldb + k0 + kk]);
            Bs[(kk + 0) * LDSH + j] = v.x;
            Bs[(kk + 1) * LDSH + j] = v.y;
            Bs[(kk + 2) * LDSH + j] = v.z;
            Bs[(kk + 3) * LDSH + j] = v.w;
        }
        __syncthreads();

#pragma unroll
        for (int k = 0; k < BK; ++k) {
            float4 av = *reinterpret_cast<const float4*>(&As[k * LDSH + ty * 4]);
            float4 bv = *reinterpret_cast<const float4*>(&Bs[k * LDSH + tx * 4]);
            float ar[4] = {av.x, av.y, av.z, av.w};
            float br[4] = {bv.x, bv.y, bv.z, bv.w};
#pragma unroll
            for (int i = 0; i < 4; ++i)
#pragma unroll
                for (int j = 0; j < 4; ++j) acc[i][j] += ar[i] * br[j];
        }
        __syncthreads();
    }

    const int row = bi + ty * 4;
    const int col = bj + tx * 4;
#pragma unroll
    for (int i = 0; i < 4; ++i) {
        float4 o = make_float4(acc[i][0], acc[i][1], acc[i][2], acc[i][3]);
        if (RELU_SB) {
            float al = alpha[row + i];
            float be = beta[row + i];
            o.x = fmaxf(fmaf(al, o.x, be), 0.f);
            o.y = fmaxf(fmaf(al, o.y, be), 0.f);
            o.z = fmaxf(fmaf(al, o.z, be), 0.f);
            o.w = fmaxf(fmaf(al, o.w, be), 0.f);
        }
        *reinterpret_cast<float4*>(&Cm[(size_t)(row + i) * ldc + col]) = o;
    }
}

// ---------------------------------------------------------------------------
// Row softmax over length-4096 rows (one block per row, 256 threads x 16 elems)
// ---------------------------------------------------------------------------
__global__ void __launch_bounds__(256) softmax_kernel(float* __restrict__ S) {
    float* row = S + (size_t)blockIdx.x * Nn;
    const int t = threadIdx.x;
    __shared__ float redm[8];
    __shared__ float reds[8];

    float v[16];
    float m = -1e30f;
#pragma unroll
    for (int u = 0; u < 16; ++u) {
        v[u] = row[t + u * 256];
        m = fmaxf(m, v[u]);
    }
#pragma unroll
    for (int o = 16; o; o >>= 1) m = fmaxf(m, __shfl_xor_sync(0xffffffffu, m, o));
    if ((t & 31) == 0) redm[t >> 5] = m;
    __syncthreads();
    m = redm[0];
#pragma unroll
    for (int w = 1; w < 8; ++w) m = fmaxf(m, redm[w]);

    float s = 0.f;
#pragma unroll
    for (int u = 0; u < 16; ++u) {
        v[u] = __expf(v[u] - m);
        s += v[u];
    }
#pragma unroll
    for (int o = 16; o; o >>= 1) s += __shfl_xor_sync(0xffffffffu, s, o);
    if ((t & 31) == 0) reds[t >> 5] = s;
    __syncthreads();
    float tot = 0.f;
#pragma unroll
    for (int w = 0; w < 8; ++w) tot += reds[w];
    float inv = 1.0f / tot;
#pragma unroll
    for (int u = 0; u < 16; ++u) row[t + u * 256] = v[u] * inv;
}

// ---------------------------------------------------------------------------
// U += F (elementwise, float4)
// ---------------------------------------------------------------------------
__global__ void add_kernel(float* __restrict__ U, const float* __restrict__ F, int n4) {
    int i = blockIdx.x * blockDim.x + threadIdx.x;
    if (i < n4) {
        float4 u = reinterpret_cast<float4*>(U)[i];
        float4 f = reinterpret_cast<const float4*>(F)[i];
        u.x += f.x; u.y += f.y; u.z += f.z; u.w += f.w;
        reinterpret_cast<float4*>(U)[i] = u;
    }
}

// ---------------------------------------------------------------------------
extern "C" void kernel_launch(void* const* d_in, const int* in_sizes, int n_in,
                              void* d_out, int out_size) {
    const float* feature = (const float*)d_in[0];
    const float* Wl[5];
    const float *gl[5], *bl[5], *ml[5], *vl[5];
    for (int L = 0; L < 5; ++L) {
        Wl[L] = (const float*)d_in[1 + 5 * L + 0];
        gl[L] = (const float*)d_in[1 + 5 * L + 1];
        bl[L] = (const float*)d_in[1 + 5 * L + 2];
        ml[L] = (const float*)d_in[1 + 5 * L + 3];
        vl[L] = (const float*)d_in[1 + 5 * L + 4];
    }

    float *pF, *pQ, *pK, *pV, *pU, *pS, *pAl, *pBe;
    cudaGetSymbolAddress((void**)&pF, g_F);
    cudaGetSymbolAddress((void**)&pQ, g_Q);
    cudaGetSymbolAddress((void**)&pK, g_K);
    cudaGetSymbolAddress((void**)&pV, g_V);
    cudaGetSymbolAddress((void**)&pU, g_U);
    cudaGetSymbolAddress((void**)&pS, g_S);
    cudaGetSymbolAddress((void**)&pAl, g_alpha);
    cudaGetSymbolAddress((void**)&pBe, g_beta);

    const int couts[5] = {Rr, Rr, Rr, Rr, Cc};  // r,q,k,v,u
    for (int L = 0; L < 5; ++L)
        prep_kernel<<<(couts[L] + 255) / 256, 256>>>(
            gl[L], bl[L], ml[L], vl[L], pAl + L * 2048, pBe + L * 2048, couts[L]);

    const long RN = (long)Rr * Nn;
    const long CN = (long)Cc * Nn;
    const long NN = (long)Nn * Nn;

    // 1) F = cbr(Wr @ X)   [512 x 4096] per batch, K=2048
    sgemm_kernel<false, false, true><<<dim3(Nn / 64, Rr / 64, Bb), 256>>>(
        Wl[0], feature, pF, Cc, Cc, Nn, Nn, 0, CN, RN, pAl + 0 * 2048, pBe + 0 * 2048);

    // 2) Q,K,V = cbr(Wx @ F)   K=512
    sgemm_kernel<false, false, true><<<dim3(Nn / 64, Rr / 64, Bb), 256>>>(
        Wl[1], pF, pQ, Rr, Rr, Nn, Nn, 0, RN, RN, pAl + 1 * 2048, pBe + 1 * 2048);
    sgemm_kernel<false, false, true><<<dim3(Nn / 64, Rr / 64, Bb), 256>>>(
        Wl[2], pF, pK, Rr, Rr, Nn, Nn, 0, RN, RN, pAl + 2 * 2048, pBe + 2 * 2048);
    sgemm_kernel<false, false, true><<<dim3(Nn / 64, Rr / 64, Bb), 256>>>(
        Wl[3], pF, pV, Rr, Rr, Nn, Nn, 0, RN, RN, pAl + 3 * 2048, pBe + 3 * 2048);

    // 3) S = Q^T K  [4096 x 4096] per batch, K=512
    sgemm_kernel<true, false, false><<<dim3(Nn / 64, Nn / 64, Bb), 256>>>(
        pQ, pK, pS, Rr, Nn, Nn, Nn, RN, RN, NN, nullptr, nullptr);

    // 4) P = softmax rows of S
    softmax_kernel<<<Bb * Nn, 256>>>(pS);

    // 5) U = V @ P^T  [512 x 4096] per batch, K=4096
    sgemm_kernel<false, true, false><<<dim3(Nn / 64, Rr / 64, Bb), 256>>>(
        pV, pS, pU, Nn, Nn, Nn, Nn, RN, NN, RN, nullptr, nullptr);

    // 6) U += F
    {
        int n4 = (int)(Bb * RN / 4);
        add_kernel<<<(n4 + 255) / 256, 256>>>(pU, pF, n4);
    }

    // 7) out = cbr(Wu @ (F+U))  [2048 x 4096] per batch, K=512
    sgemm_kernel<false, false, true><<<dim3(Nn / 64, Cc / 64, Bb), 256>>>(
        Wl[4], pU, (float*)d_out, Rr, Rr, Nn, Nn, 0, RN, CN,
        pAl + 4 * 2048, pBe + 4 * 2048);
}

// round 3
// speedup vs baseline: 1.0543x; 1.0543x over previous
#include <cuda_runtime.h>
#include <cuda_bf16.h>
#include <cstdint>
#include <cstddef>

#define EPS_BN 1e-5f

constexpr int Bb = 4;
constexpr int Cc = 2048;
constexpr int Rr = 512;
constexpr int Nn = 4096;   // H*W

// Scratch (allocation-free: __device__ globals)
__device__ float g_F[(size_t)Bb * Rr * Nn];
__device__ float g_Q[(size_t)Bb * Rr * Nn];
__device__ float g_K[(size_t)Bb * Rr * Nn];
__device__ float g_V[(size_t)Bb * Rr * Nn];
__device__ float g_U[(size_t)Bb * Rr * Nn];
__device__ float g_S[(size_t)Bb * Nn * Nn];
__device__ float g_alpha[5 * 2048];
__device__ float g_beta[5 * 2048];

// ===================== helpers =====================
__device__ __forceinline__ uint32_t smem_u32(const void* p) {
    uint32_t a;
    asm("{ .reg .u64 t; cvta.to.shared.u64 t, %1; cvt.u32.u64 %0, t; }" : "=r"(a) : "l"(p));
    return a;
}

__device__ __forceinline__ void ldsm4(uint32_t* r, uint32_t addr) {
    asm volatile("ldmatrix.sync.aligned.m8n8.x4.shared.b16 {%0,%1,%2,%3}, [%4];"
                 : "=r"(r[0]), "=r"(r[1]), "=r"(r[2]), "=r"(r[3]) : "r"(addr));
}

__device__ __forceinline__ void mma_bf16(float* c, const uint32_t* a, uint32_t b0, uint32_t b1) {
    asm volatile(
        "mma.sync.aligned.m16n8k16.row.col.f32.bf16.bf16.f32 "
        "{%0,%1,%2,%3}, {%4,%5,%6,%7}, {%8,%9}, {%0,%1,%2,%3};"
        : "+f"(c[0]), "+f"(c[1]), "+f"(c[2]), "+f"(c[3])
        : "r"(a[0]), "r"(a[1]), "r"(a[2]), "r"(a[3]), "r"(b0), "r"(b1));
}

// ===================== BN fold =====================
__global__ void prep_kernel(const float* __restrict__ g, const float* __restrict__ b,
                            const float* __restrict__ m, const float* __restrict__ v,
                            float* __restrict__ al, float* __restrict__ be, int n) {
    int i = blockIdx.x * blockDim.x + threadIdx.x;
    if (i < n) {
        float a = g[i] * rsqrtf(v[i] + EPS_BN);
        al[i] = a;
        be[i] = b[i] - m[i] * a;
    }
}

// ===================== bf16-split MMA GEMM =====================
// C[i,j] = sum_k Aop[i,k]*Bop[k,j], fp32 in/out, 2-term bf16 split (3 products).
//   TAT=false: A gmem [m][k] (k contiguous). TAT=true: A gmem [k][m] (m contiguous).
//   TBKN=true: B gmem [k][n] (n contiguous). TBKN=false: B gmem [n][k] (k contiguous).
// Block tile 128x128, BK=32, 256 threads (8 warps: 2 x 4, warp tile 64x32).
constexpr int SSTR = 40;  // smem row stride in bf16 elems (padded; conflict-free ldmatrix)

template <bool TAT, bool TBKN, bool RELU>
__global__ void __launch_bounds__(256) mma_gemm(
    const float* __restrict__ A, const float* __restrict__ B, float* __restrict__ C,
    int K, int lda, int ldb, int ldc, long sA, long sB, long sC,
    const float* __restrict__ alpha, const float* __restrict__ beta) {
    __shared__ __nv_bfloat16 sAh[128 * SSTR], sAl[128 * SSTR];
    __shared__ __nv_bfloat16 sBh[128 * SSTR], sBl[128 * SSTR];

    const int t = threadIdx.x;
    const int lane = t & 31;
    const int wid = t >> 5;
    const int warp_m = wid >> 2;   // 0..1 -> m offset 64*warp_m
    const int warp_n = wid & 3;    // 0..3 -> n offset 32*warp_n
    const int bi = blockIdx.y * 128;
    const int bj = blockIdx.x * 128;
    A += sA * blockIdx.z;
    B += sB * blockIdx.z;
    C += sC * blockIdx.z;

    const uint32_t uAh = smem_u32(sAh), uAl = smem_u32(sAl);
    const uint32_t uBh = smem_u32(sBh), uBl = smem_u32(sBl);

    float acc[4][4][4] = {};
    float4 ar[4], br[4];
    const int T = K / 32;

    // ---- prefetch tile 0 ----
#pragma unroll
    for (int i = 0; i < 4; ++i) {
        int p = t + 256 * i;
        if (!TAT) { int m = p >> 3, k4 = (p & 7) * 4;
            ar[i] = *reinterpret_cast<const float4*>(&A[(size_t)(bi + m) * lda + k4]); }
        else { int m4 = (p & 31) * 4, k = p >> 5;
            ar[i] = *reinterpret_cast<const float4*>(&A[(size_t)k * lda + bi + m4]); }
        if (TBKN) { int n4 = (p & 31) * 4, k = p >> 5;
            br[i] = *reinterpret_cast<const float4*>(&B[(size_t)k * ldb + bj + n4]); }
        else { int n = p >> 3, k4 = (p & 7) * 4;
            br[i] = *reinterpret_cast<const float4*>(&B[(size_t)(bj + n) * ldb + k4]); }
    }

    for (int tt = 0; tt < T; ++tt) {
        // ---- convert + STS current tile ----
#pragma unroll
        for (int i = 0; i < 4; ++i) {
            int p = t + 256 * i;
            // A
            {
                float4 v = ar[i];
                __nv_bfloat162 h01 = __floats2bfloat162_rn(v.x, v.y);
                __nv_bfloat162 h23 = __floats2bfloat162_rn(v.z, v.w);
                __nv_bfloat162 l01 = __floats2bfloat162_rn(v.x - __bfloat162float(h01.x),
                                                           v.y - __bfloat162float(h01.y));
                __nv_bfloat162 l23 = __floats2bfloat162_rn(v.z - __bfloat162float(h23.x),
                                                           v.w - __bfloat162float(h23.y));
                if (!TAT) {
                    int m = p >> 3, k4 = (p & 7) * 4;
                    *reinterpret_cast<__nv_bfloat162*>(&sAh[m * SSTR + k4]) = h01;
                    *reinterpret_cast<__nv_bfloat162*>(&sAh[m * SSTR + k4 + 2]) = h23;
                    *reinterpret_cast<__nv_bfloat162*>(&sAl[m * SSTR + k4]) = l01;
                    *reinterpret_cast<__nv_bfloat162*>(&sAl[m * SSTR + k4 + 2]) = l23;
                } else {
                    int m4 = (p & 31) * 4, k = p >> 5;
                    sAh[(m4 + 0) * SSTR + k] = h01.x; sAl[(m4 + 0) * SSTR + k] = l01.x;
                    sAh[(m4 + 1) * SSTR + k] = h01.y; sAl[(m4 + 1) * SSTR + k] = l01.y;
                    sAh[(m4 + 2) * SSTR + k] = h23.x; sAl[(m4 + 2) * SSTR + k] = l23.x;
                    sAh[(m4 + 3) * SSTR + k] = h23.y; sAl[(m4 + 3) * SSTR + k] = l23.y;
                }
            }
            // B
            {
                float4 v = br[i];
                __nv_bfloat162 h01 = __floats2bfloat162_rn(v.x, v.y);
                __nv_bfloat162 h23 = __floats2bfloat162_rn(v.z, v.w);
                __nv_bfloat162 l01 = __floats2bfloat162_rn(v.x - __bfloat162float(h01.x),
                                                           v.y - __bfloat162float(h01.y));
                __nv_bfloat162 l23 = __floats2bfloat162_rn(v.z - __bfloat162float(h23.x),
                                                           v.w - __bfloat162float(h23.y));
                if (TBKN) {
                    int n4 = (p & 31) * 4, k = p >> 5;
                    sBh[(n4 + 0) * SSTR + k] = h01.x; sBl[(n4 + 0) * SSTR + k] = l01.x;
                    sBh[(n4 + 1) * SSTR + k] = h01.y; sBl[(n4 + 1) * SSTR + k] = l01.y;
                    sBh[(n4 + 2) * SSTR + k] = h23.x; sBl[(n4 + 2) * SSTR + k] = l23.x;
                    sBh[(n4 + 3) * SSTR + k] = h23.y; sBl[(n4 + 3) * SSTR + k] = l23.y;
                } else {
                    int n = p >> 3, k4 = (p & 7) * 4;
                    *reinterpret_cast<__nv_bfloat162*>(&sBh[n * SSTR + k4]) = h01;
                    *reinterpret_cast<__nv_bfloat162*>(&sBh[n * SSTR + k4 + 2]) = h23;
                    *reinterpret_cast<__nv_bfloat162*>(&sBl[n * SSTR + k4]) = l01;
                    *reinterpret_cast<__nv_bfloat162*>(&sBl[n * SSTR + k4 + 2]) = l23;
                }
            }
        }
        __syncthreads();

        // ---- prefetch next tile (LDG latency hidden by MMA below) ----
        if (tt + 1 < T) {
            const int k0 = (tt + 1) * 32;
#pragma unroll
            for (int i = 0; i < 4; ++i) {
                int p = t + 256 * i;
                if (!TAT) { int m = p >> 3, k4 = (p & 7) * 4;
                    ar[i] = *reinterpret_cast<const float4*>(&A[(size_t)(bi + m) * lda + k0 + k4]); }
                else { int m4 = (p & 31) * 4, k = p >> 5;
                    ar[i] = *reinterpret_cast<const float4*>(&A[(size_t)(k0 + k) * lda + bi + m4]); }
                if (TBKN) { int n4 = (p & 31) * 4, k = p >> 5;
                    br[i] = *reinterpret_cast<const float4*>(&B[(size_t)(k0 + k) * ldb + bj + n4]); }
                else { int n = p >> 3, k4 = (p & 7) * 4;
                    br[i] = *reinterpret_cast<const float4*>(&B[(size_t)(bj + n) * ldb + k0 + k4]); }
            }
        }

        // ---- MMA: 2 k16 steps x 3 products (hh, lh, hl) ----
#pragma unroll
        for (int ks = 0; ks < 2; ++ks) {
            const uint32_t cofs = (uint32_t)((ks * 16 + (lane >> 4) * 8) * 2);
            const uint32_t arow = (uint32_t)((warp_m * 64 + (lane & 15)) * SSTR * 2);
            const uint32_t brow = (uint32_t)((warp_n * 32 + (lane & 15)) * SSTR * 2);

            uint32_t af[4][4], bfh[2][4];
#pragma unroll
            for (int mt = 0; mt < 4; ++mt)
                ldsm4(af[mt], uAh + arow + (uint32_t)(mt * 16 * SSTR * 2) + cofs);
#pragma unroll
            for (int np = 0; np < 2; ++np)
                ldsm4(bfh[np], uBh + brow + (uint32_t)(np * 16 * SSTR * 2) + cofs);
            // hh
#pragma unroll
            for (int mt = 0; mt < 4; ++mt)
#pragma unroll
                for (int nt = 0; nt < 4; ++nt)
                    mma_bf16(acc[mt][nt], af[mt], bfh[nt >> 1][nt & 1], bfh[nt >> 1][2 + (nt & 1)]);
            // lh  (Al x Bh)
            {
                uint32_t al_[4][4];
#pragma unroll
                for (int mt = 0; mt < 4; ++mt)
                    ldsm4(al_[mt], uAl + arow + (uint32_t)(mt * 16 * SSTR * 2) + cofs);
#pragma unroll
                for (int mt = 0; mt < 4; ++mt)
#pragma unroll
                    for (int nt = 0; nt < 4; ++nt)
                        mma_bf16(acc[mt][nt], al_[mt], bfh[nt >> 1][nt & 1], bfh[nt >> 1][2 + (nt & 1)]);
            }
            // hl  (Ah x Bl)
            {
                uint32_t bfl[2][4];
#pragma unroll
                for (int np = 0; np < 2; ++np)
                    ldsm4(bfl[np], uBl + brow + (uint32_t)(np * 16 * SSTR * 2) + cofs);
#pragma unroll
                for (int mt = 0; mt < 4; ++mt)
#pragma unroll
                    for (int nt = 0; nt < 4; ++nt)
                        mma_bf16(acc[mt][nt], af[mt], bfl[nt >> 1][nt & 1], bfl[nt >> 1][2 + (nt & 1)]);
            }
        }
        __syncthreads();
    }

    // ---- epilogue ----
#pragma unroll
    for (int mt = 0; mt < 4; ++mt) {
        const int m0 = bi + warp_m * 64 + mt * 16 + (lane >> 2);
        float a0 = 1.f, b0 = 0.f, a1 = 1.f, b1 = 0.f;
        if (RELU) {
            a0 = alpha[m0]; b0 = beta[m0];
            a1 = alpha[m0 + 8]; b1 = beta[m0 + 8];
        }
#pragma unroll
        for (int nt = 0; nt < 4; ++nt) {
            const int n = bj + warp_n * 32 + nt * 8 + (lane & 3) * 2;
            float c0 = acc[mt][nt][0], c1 = acc[mt][nt][1];
            float c2 = acc[mt][nt][2], c3 = acc[mt][nt][3];
            if (RELU) {
                c0 = fmaxf(fmaf(a0, c0, b0), 0.f); c1 = fmaxf(fmaf(a0, c1, b0), 0.f);
                c2 = fmaxf(fmaf(a1, c2, b1), 0.f); c3 = fmaxf(fmaf(a1, c3, b1), 0.f);
            }
            *reinterpret_cast<float2*>(&C[(size_t)m0 * ldc + n]) = make_float2(c0, c1);
            *reinterpret_cast<float2*>(&C[(size_t)(m0 + 8) * ldc + n]) = make_float2(c2, c3);
        }
    }
}

// ===================== softmax over length-4096 rows =====================
__global__ void __launch_bounds__(256) softmax_kernel(float* __restrict__ S) {
    float* row = S + (size_t)blockIdx.x * Nn;
    const int t = threadIdx.x;
    __shared__ float redm[8];
    __shared__ float reds[8];

    float v[16];
    float m = -1e30f;
#pragma unroll
    for (int u = 0; u < 16; ++u) {
        v[u] = row[t + u * 256];
        m = fmaxf(m, v[u]);
    }
#pragma unroll
    for (int o = 16; o; o >>= 1) m = fmaxf(m, __shfl_xor_sync(0xffffffffu, m, o));
    if ((t & 31) == 0) redm[t >> 5] = m;
    __syncthreads();
    m = redm[0];
#pragma unroll
    for (int w = 1; w < 8; ++w) m = fmaxf(m, redm[w]);

    float s = 0.f;
#pragma unroll
    for (int u = 0; u < 16; ++u) {
        v[u] = __expf(v[u] - m);
        s += v[u];
    }
#pragma unroll
    for (int o = 16; o; o >>= 1) s += __shfl_xor_sync(0xffffffffu, s, o);
    if ((t & 31) == 0) reds[t >> 5] = s;
    __syncthreads();
    float tot = 0.f;
#pragma unroll
    for (int w = 0; w < 8; ++w) tot += reds[w];
    float inv = 1.0f / tot;
#pragma unroll
    for (int u = 0; u < 16; ++u) row[t + u * 256] = v[u] * inv;
}

__global__ void add_kernel(float* __restrict__ U, const float* __restrict__ F, int n4) {
    int i = blockIdx.x * blockDim.x + threadIdx.x;
    if (i < n4) {
        float4 u = reinterpret_cast<float4*>(U)[i];
        float4 f = reinterpret_cast<const float4*>(F)[i];
        u.x += f.x; u.y += f.y; u.z += f.z; u.w += f.w;
        reinterpret_cast<float4*>(U)[i] = u;
    }
}

// ===================== host =====================
extern "C" void kernel_launch(void* const* d_in, const int* in_sizes, int n_in,
                              void* d_out, int out_size) {
    const float* feature = (const float*)d_in[0];
    const float* Wl[5];
    const float *gl[5], *bl[5], *ml[5], *vl[5];
    for (int L = 0; L < 5; ++L) {
        Wl[L] = (const float*)d_in[1 + 5 * L + 0];
        gl[L] = (const float*)d_in[1 + 5 * L + 1];
        bl[L] = (const float*)d_in[1 + 5 * L + 2];
        ml[L] = (const float*)d_in[1 + 5 * L + 3];
        vl[L] = (const float*)d_in[1 + 5 * L + 4];
    }

    float *pF, *pQ, *pK, *pV, *pU, *pS, *pAl, *pBe;
    cudaGetSymbolAddress((void**)&pF, g_F);
    cudaGetSymbolAddress((void**)&pQ, g_Q);
    cudaGetSymbolAddress((void**)&pK, g_K);
    cudaGetSymbolAddress((void**)&pV, g_V);
    cudaGetSymbolAddress((void**)&pU, g_U);
    cudaGetSymbolAddress((void**)&pS, g_S);
    cudaGetSymbolAddress((void**)&pAl, g_alpha);
    cudaGetSymbolAddress((void**)&pBe, g_beta);

    const int couts[5] = {Rr, Rr, Rr, Rr, Cc};
    for (int L = 0; L < 5; ++L)
        prep_kernel<<<(couts[L] + 255) / 256, 256>>>(
            gl[L], bl[L], ml[L], vl[L], pAl + L * 2048, pBe + L * 2048, couts[L]);

    const long RN = (long)Rr * Nn;
    const long CN = (long)Cc * Nn;
    const long NN = (long)Nn * Nn;

    // 1) F = cbr(Wr @ X)  M=512, K=2048
    mma_gemm<false, true, true><<<dim3(Nn / 128, Rr / 128, Bb), 256>>>(
        Wl[0], feature, pF, Cc, Cc, Nn, Nn, 0, CN, RN, pAl + 0 * 2048, pBe + 0 * 2048);

    // 2-4) Q,K,V = cbr(W @ F)  M=512, K=512
    mma_gemm<false, true, true><<<dim3(Nn / 128, Rr / 128, Bb), 256>>>(
        Wl[1], pF, pQ, Rr, Rr, Nn, Nn, 0, RN, RN, pAl + 1 * 2048, pBe + 1 * 2048);
    mma_gemm<false, true, true><<<dim3(Nn / 128, Rr / 128, Bb), 256>>>(
        Wl[2], pF, pK, Rr, Rr, Nn, Nn, 0, RN, RN, pAl + 2 * 2048, pBe + 2 * 2048);
    mma_gemm<false, true, true><<<dim3(Nn / 128, Rr / 128, Bb), 256>>>(
        Wl[3], pF, pV, Rr, Rr, Nn, Nn, 0, RN, RN, pAl + 3 * 2048, pBe + 3 * 2048);

    // 5) S = Q^T K  M=4096, K=512  (A = Q in [k][m] layout -> TAT)
    mma_gemm<true, true, false><<<dim3(Nn / 128, Nn / 128, Bb), 256>>>(
        pQ, pK, pS, Rr, Nn, Nn, Nn, RN, RN, NN, nullptr, nullptr);

    // 6) P = softmax rows of S
    softmax_kernel<<<Bb * Nn, 256>>>(pS);

    // 7) U = V @ P^T  M=512, K=4096  (B = P already [n][k] -> TBKN=false)
    mma_gemm<false, false, false><<<dim3(Nn / 128, Rr / 128, Bb), 256>>>(
        pV, pS, pU, Nn, Nn, Nn, Nn, RN, NN, RN, nullptr, nullptr);

    // 8) U += F
    {
        int n4 = (int)(Bb * RN / 4);
        add_kernel<<<(n4 + 255) / 256, 256>>>(pU, pF, n4);
    }

    // 9) out = cbr(Wu @ (F+U))  M=2048, K=512
    mma_gemm<false, true, true><<<dim3(Nn / 128, Cc / 128, Bb), 256>>>(
        Wl[4], pU, (float*)d_out, Rr, Rr, Nn, Nn, 0, RN, CN,
        pAl + 4 * 2048, pBe + 4 * 2048);
}

// round 4
// speedup vs baseline: 1.1623x; 1.1024x over previous
#include <cuda_runtime.h>
#include <cuda_bf16.h>
#include <cstdint>
#include <cstddef>

#define EPS_BN 1e-5f

constexpr int Bb = 4;
constexpr int Cc = 2048;
constexpr int Rr = 512;
constexpr int Nn = 4096;   // H*W

// Scratch (allocation-free: __device__ globals)
__device__ float g_F[(size_t)Bb * Rr * Nn];
__device__ float g_Q[(size_t)Bb * Rr * Nn];
__device__ float g_K[(size_t)Bb * Rr * Nn];
__device__ float g_V[(size_t)Bb * Rr * Nn];
__device__ float g_U[(size_t)Bb * Rr * Nn];
__device__ float g_S[(size_t)Bb * Nn * Nn];
__device__ float g_alpha[5 * 2048];
__device__ float g_beta[5 * 2048];

// ===================== helpers =====================
__device__ __forceinline__ uint32_t smem_u32(const void* p) {
    uint32_t a;
    asm("{ .reg .u64 t; cvta.to.shared.u64 t, %1; cvt.u32.u64 %0, t; }" : "=r"(a) : "l"(p));
    return a;
}

__device__ __forceinline__ void ldsm4(uint32_t* r, uint32_t addr) {
    asm volatile("ldmatrix.sync.aligned.m8n8.x4.shared.b16 {%0,%1,%2,%3}, [%4];"
                 : "=r"(r[0]), "=r"(r[1]), "=r"(r[2]), "=r"(r[3]) : "r"(addr));
}

__device__ __forceinline__ void mma_bf16(float* c, const uint32_t* a, uint32_t b0, uint32_t b1) {
    asm volatile(
        "mma.sync.aligned.m16n8k16.row.col.f32.bf16.bf16.f32 "
        "{%0,%1,%2,%3}, {%4,%5,%6,%7}, {%8,%9}, {%0,%1,%2,%3};"
        : "+f"(c[0]), "+f"(c[1]), "+f"(c[2]), "+f"(c[3])
        : "r"(a[0]), "r"(a[1]), "r"(a[2]), "r"(a[3]), "r"(b0), "r"(b1));
}

// ===================== BN fold =====================
__global__ void prep_kernel(const float* __restrict__ g, const float* __restrict__ b,
                            const float* __restrict__ m, const float* __restrict__ v,
                            float* __restrict__ al, float* __restrict__ be, int n) {
    int i = blockIdx.x * blockDim.x + threadIdx.x;
    if (i < n) {
        float a = g[i] * rsqrtf(v[i] + EPS_BN);
        al[i] = a;
        be[i] = b[i] - m[i] * a;
    }
}

// ===================== bf16-split MMA GEMM (double-buffered, 512 thr) ========
// C[i,j] = sum_k Aop[i,k]*Bop[k,j], fp32 in/out, 2-term bf16 split (3 products).
//   TAT=false: A gmem [m][k].  TAT=true: A gmem [k][m].
//   TBKN=true: B gmem [k][n].  TBKN=false: B gmem [n][k].
// Block tile 128x128, BK=32, 512 threads (16 warps, warp tile 32x32).
constexpr int SSTR = 40;                  // smem row stride (bf16 elems)
constexpr int ARR = 128 * SSTR;           // elems per array (10240 B)
constexpr int BUF = 4 * ARR;              // one stage: Ah,Al,Bh,Bl (40960 B)
constexpr int SMEM_SZ = 2 * BUF * 2;      // bytes: 2 stages

template <bool TAT, bool TBKN, bool RELU>
__global__ void __launch_bounds__(512, 1) mma_gemm(
    const float* __restrict__ A, const float* __restrict__ B, float* __restrict__ C,
    int K, int lda, int ldb, int ldc, long sA, long sB, long sC,
    const float* __restrict__ alpha, const float* __restrict__ beta) {
    extern __shared__ __nv_bfloat16 smem[];

    const int t = threadIdx.x;
    const int lane = t & 31;
    const int wid = t >> 5;
    const int warp_m = wid >> 2;   // 0..3 -> m offset 32*warp_m
    const int warp_n = wid & 3;    // 0..3 -> n offset 32*warp_n
    const int bi = blockIdx.y * 128;
    const int bj = blockIdx.x * 128;
    A += sA * blockIdx.z;
    B += sB * blockIdx.z;
    C += sC * blockIdx.z;

    const uint32_t su = smem_u32(smem);
    const int T = K / 32;

    float acc[2][4][4] = {};
    float4 ar[2], br[2];

    // ---------- helpers as lambdas ----------
    auto ldg_tile = [&](int k0) {
#pragma unroll
        for (int i = 0; i < 2; ++i) {
            int p = t + 512 * i;
            if (!TAT) { int m = p >> 3, k4 = (p & 7) * 4;
                ar[i] = *reinterpret_cast<const float4*>(&A[(size_t)(bi + m) * lda + k0 + k4]); }
            else { int m4 = (p & 31) * 4, k = p >> 5;
                ar[i] = *reinterpret_cast<const float4*>(&A[(size_t)(k0 + k) * lda + bi + m4]); }
            if (TBKN) { int n4 = (p & 31) * 4, k = p >> 5;
                br[i] = *reinterpret_cast<const float4*>(&B[(size_t)(k0 + k) * ldb + bj + n4]); }
            else { int n = p >> 3, k4 = (p & 7) * 4;
                br[i] = *reinterpret_cast<const float4*>(&B[(size_t)(bj + n) * ldb + k0 + k4]); }
        }
    };

    auto sts_tile = [&](int stage) {
        __nv_bfloat16* sAh = smem + stage * BUF;
        __nv_bfloat16* sAl = sAh + ARR;
        __nv_bfloat16* sBh = sAl + ARR;
        __nv_bfloat16* sBl = sBh + ARR;
#pragma unroll
        for (int i = 0; i < 2; ++i) {
            int p = t + 512 * i;
            {
                float4 v = ar[i];
                __nv_bfloat162 h01 = __floats2bfloat162_rn(v.x, v.y);
                __nv_bfloat162 h23 = __floats2bfloat162_rn(v.z, v.w);
                __nv_bfloat162 l01 = __floats2bfloat162_rn(v.x - __bfloat162float(h01.x),
                                                           v.y - __bfloat162float(h01.y));
                __nv_bfloat162 l23 = __floats2bfloat162_rn(v.z - __bfloat162float(h23.x),
                                                           v.w - __bfloat162float(h23.y));
                if (!TAT) {
                    int m = p >> 3, k4 = (p & 7) * 4;
                    *reinterpret_cast<__nv_bfloat162*>(&sAh[m * SSTR + k4]) = h01;
                    *reinterpret_cast<__nv_bfloat162*>(&sAh[m * SSTR + k4 + 2]) = h23;
                    *reinterpret_cast<__nv_bfloat162*>(&sAl[m * SSTR + k4]) = l01;
                    *reinterpret_cast<__nv_bfloat162*>(&sAl[m * SSTR + k4 + 2]) = l23;
                } else {
                    int m4 = (p & 31) * 4, k = p >> 5;
                    sAh[(m4 + 0) * SSTR + k] = h01.x; sAl[(m4 + 0) * SSTR + k] = l01.x;
                    sAh[(m4 + 1) * SSTR + k] = h01.y; sAl[(m4 + 1) * SSTR + k] = l01.y;
                    sAh[(m4 + 2) * SSTR + k] = h23.x; sAl[(m4 + 2) * SSTR + k] = l23.x;
                    sAh[(m4 + 3) * SSTR + k] = h23.y; sAl[(m4 + 3) * SSTR + k] = l23.y;
                }
            }
            {
                float4 v = br[i];
                __nv_bfloat162 h01 = __floats2bfloat162_rn(v.x, v.y);
                __nv_bfloat162 h23 = __floats2bfloat162_rn(v.z, v.w);
                __nv_bfloat162 l01 = __floats2bfloat162_rn(v.x - __bfloat162float(h01.x),
                                                           v.y - __bfloat162float(h01.y));
                __nv_bfloat162 l23 = __floats2bfloat162_rn(v.z - __bfloat162float(h23.x),
                                                           v.w - __bfloat162float(h23.y));
                if (TBKN) {
                    int n4 = (p & 31) * 4, k = p >> 5;
                    sBh[(n4 + 0) * SSTR + k] = h01.x; sBl[(n4 + 0) * SSTR + k] = l01.x;
                    sBh[(n4 + 1) * SSTR + k] = h01.y; sBl[(n4 + 1) * SSTR + k] = l01.y;
                    sBh[(n4 + 2) * SSTR + k] = h23.x; sBl[(n4 + 2) * SSTR + k] = l23.x;
                    sBh[(n4 + 3) * SSTR + k] = h23.y; sBl[(n4 + 3) * SSTR + k] = l23.y;
                } else {
                    int n = p >> 3, k4 = (p & 7) * 4;
                    *reinterpret_cast<__nv_bfloat162*>(&sBh[n * SSTR + k4]) = h01;
                    *reinterpret_cast<__nv_bfloat162*>(&sBh[n * SSTR + k4 + 2]) = h23;
                    *reinterpret_cast<__nv_bfloat162*>(&sBl[n * SSTR + k4]) = l01;
                    *reinterpret_cast<__nv_bfloat162*>(&sBl[n * SSTR + k4 + 2]) = l23;
                }
            }
        }
    };

    // ---------- prologue ----------
    ldg_tile(0);
    sts_tile(0);
    __syncthreads();

    const uint32_t arow0 = (uint32_t)((warp_m * 32 + (lane & 15)) * SSTR * 2);
    const uint32_t brow0 = (uint32_t)((warp_n * 32 + (lane & 15)) * SSTR * 2);
    const uint32_t lofs = (uint32_t)(((lane >> 4) * 8) * 2);

    for (int tt = 0; tt < T; ++tt) {
        const int p = tt & 1;
        if (tt + 1 < T) ldg_tile((tt + 1) * 32);

        const uint32_t sb = su + (uint32_t)(p * BUF * 2);
        const uint32_t uAh = sb, uAl = sb + ARR * 2;
        const uint32_t uBh = sb + 2 * ARR * 2, uBl = sb + 3 * ARR * 2;

#pragma unroll
        for (int ks = 0; ks < 2; ++ks) {
            const uint32_t cofs = (uint32_t)(ks * 32) + lofs;
            uint32_t af[2][4], alr[2][4], bfh[2][4], bfl[2][4];
#pragma unroll
            for (int mt = 0; mt < 2; ++mt) {
                ldsm4(af[mt], uAh + arow0 + (uint32_t)(mt * 16 * SSTR * 2) + cofs);
                ldsm4(alr[mt], uAl + arow0 + (uint32_t)(mt * 16 * SSTR * 2) + cofs);
            }
#pragma unroll
            for (int np = 0; np < 2; ++np) {
                ldsm4(bfh[np], uBh + brow0 + (uint32_t)(np * 16 * SSTR * 2) + cofs);
                ldsm4(bfl[np], uBl + brow0 + (uint32_t)(np * 16 * SSTR * 2) + cofs);
            }
#pragma unroll
            for (int mt = 0; mt < 2; ++mt)
#pragma unroll
                for (int nt = 0; nt < 4; ++nt) {
                    uint32_t b0h = bfh[nt >> 1][nt & 1], b1h = bfh[nt >> 1][2 + (nt & 1)];
                    mma_bf16(acc[mt][nt], af[mt], b0h, b1h);
                    mma_bf16(acc[mt][nt], alr[mt], b0h, b1h);
                    mma_bf16(acc[mt][nt], af[mt], bfl[nt >> 1][nt & 1], bfl[nt >> 1][2 + (nt & 1)]);
                }
        }

        if (tt + 1 < T) sts_tile(p ^ 1);
        __syncthreads();
    }

    // ---------- epilogue ----------
#pragma unroll
    for (int mt = 0; mt < 2; ++mt) {
        const int m0 = bi + warp_m * 32 + mt * 16 + (lane >> 2);
        float a0 = 1.f, b0 = 0.f, a1 = 1.f, b1 = 0.f;
        if (RELU) {
            a0 = alpha[m0]; b0 = beta[m0];
            a1 = alpha[m0 + 8]; b1 = beta[m0 + 8];
        }
#pragma unroll
        for (int nt = 0; nt < 4; ++nt) {
            const int n = bj + warp_n * 32 + nt * 8 + (lane & 3) * 2;
            float c0 = acc[mt][nt][0], c1 = acc[mt][nt][1];
            float c2 = acc[mt][nt][2], c3 = acc[mt][nt][3];
            if (RELU) {
                c0 = fmaxf(fmaf(a0, c0, b0), 0.f); c1 = fmaxf(fmaf(a0, c1, b0), 0.f);
                c2 = fmaxf(fmaf(a1, c2, b1), 0.f); c3 = fmaxf(fmaf(a1, c3, b1), 0.f);
            }
            *reinterpret_cast<float2*>(&C[(size_t)m0 * ldc + n]) = make_float2(c0, c1);
            *reinterpret_cast<float2*>(&C[(size_t)(m0 + 8) * ldc + n]) = make_float2(c2, c3);
        }
    }
}

// ===================== softmax over length-4096 rows =====================
__global__ void __launch_bounds__(256) softmax_kernel(float* __restrict__ S) {
    float* row = S + (size_t)blockIdx.x * Nn;
    const int t = threadIdx.x;
    __shared__ float redm[8];
    __shared__ float reds[8];

    float v[16];
    float m = -1e30f;
#pragma unroll
    for (int u = 0; u < 16; ++u) {
        v[u] = row[t + u * 256];
        m = fmaxf(m, v[u]);
    }
#pragma unroll
    for (int o = 16; o; o >>= 1) m = fmaxf(m, __shfl_xor_sync(0xffffffffu, m, o));
    if ((t & 31) == 0) redm[t >> 5] = m;
    __syncthreads();
    m = redm[0];
#pragma unroll
    for (int w = 1; w < 8; ++w) m = fmaxf(m, redm[w]);

    float s = 0.f;
#pragma unroll
    for (int u = 0; u < 16; ++u) {
        v[u] = __expf(v[u] - m);
        s += v[u];
    }
#pragma unroll
    for (int o = 16; o; o >>= 1) s += __shfl_xor_sync(0xffffffffu, s, o);
    if ((t & 31) == 0) reds[t >> 5] = s;
    __syncthreads();
    float tot = 0.f;
#pragma unroll
    for (int w = 0; w < 8; ++w) tot += reds[w];
    float inv = 1.0f / tot;
#pragma unroll
    for (int u = 0; u < 16; ++u) row[t + u * 256] = v[u] * inv;
}

__global__ void add_kernel(float* __restrict__ U, const float* __restrict__ F, int n4) {
    int i = blockIdx.x * blockDim.x + threadIdx.x;
    if (i < n4) {
        float4 u = reinterpret_cast<float4*>(U)[i];
        float4 f = reinterpret_cast<const float4*>(F)[i];
        u.x += f.x; u.y += f.y; u.z += f.z; u.w += f.w;
        reinterpret_cast<float4*>(U)[i] = u;
    }
}

// ===================== host =====================
extern "C" void kernel_launch(void* const* d_in, const int* in_sizes, int n_in,
                              void* d_out, int out_size) {
    const float* feature = (const float*)d_in[0];
    const float* Wl[5];
    const float *gl[5], *bl[5], *ml[5], *vl[5];
    for (int L = 0; L < 5; ++L) {
        Wl[L] = (const float*)d_in[1 + 5 * L + 0];
        gl[L] = (const float*)d_in[1 + 5 * L + 1];
        bl[L] = (const float*)d_in[1 + 5 * L + 2];
        ml[L] = (const float*)d_in[1 + 5 * L + 3];
        vl[L] = (const float*)d_in[1 + 5 * L + 4];
    }

    float *pF, *pQ, *pK, *pV, *pU, *pS, *pAl, *pBe;
    cudaGetSymbolAddress((void**)&pF, g_F);
    cudaGetSymbolAddress((void**)&pQ, g_Q);
    cudaGetSymbolAddress((void**)&pK, g_K);
    cudaGetSymbolAddress((void**)&pV, g_V);
    cudaGetSymbolAddress((void**)&pU, g_U);
    cudaGetSymbolAddress((void**)&pS, g_S);
    cudaGetSymbolAddress((void**)&pAl, g_alpha);
    cudaGetSymbolAddress((void**)&pBe, g_beta);

    cudaFuncSetAttribute(mma_gemm<false, true, true>,
                         cudaFuncAttributeMaxDynamicSharedMemorySize, SMEM_SZ);
    cudaFuncSetAttribute(mma_gemm<true, true, false>,
                         cudaFuncAttributeMaxDynamicSharedMemorySize, SMEM_SZ);
    cudaFuncSetAttribute(mma_gemm<false, false, false>,
                         cudaFuncAttributeMaxDynamicSharedMemorySize, SMEM_SZ);

    const int couts[5] = {Rr, Rr, Rr, Rr, Cc};
    for (int L = 0; L < 5; ++L)
        prep_kernel<<<(couts[L] + 255) / 256, 256>>>(
            gl[L], bl[L], ml[L], vl[L], pAl + L * 2048, pBe + L * 2048, couts[L]);

    const long RN = (long)Rr * Nn;
    const long CN = (long)Cc * Nn;
    const long NN = (long)Nn * Nn;

    // 1) F = cbr(Wr @ X)  M=512, K=2048
    mma_gemm<false, true, true><<<dim3(Nn / 128, Rr / 128, Bb), 512, SMEM_SZ>>>(
        Wl[0], feature, pF, Cc, Cc, Nn, Nn, 0, CN, RN, pAl + 0 * 2048, pBe + 0 * 2048);

    // 2-4) Q,K,V = cbr(W @ F)  M=512, K=512
    mma_gemm<false, true, true><<<dim3(Nn / 128, Rr / 128, Bb), 512, SMEM_SZ>>>(
        Wl[1], pF, pQ, Rr, Rr, Nn, Nn, 0, RN, RN, pAl + 1 * 2048, pBe + 1 * 2048);
    mma_gemm<false, true, true><<<dim3(Nn / 128, Rr / 128, Bb), 512, SMEM_SZ>>>(
        Wl[2], pF, pK, Rr, Rr, Nn, Nn, 0, RN, RN, pAl + 2 * 2048, pBe + 2 * 2048);
    mma_gemm<false, true, true><<<dim3(Nn / 128, Rr / 128, Bb), 512, SMEM_SZ>>>(
        Wl[3], pF, pV, Rr, Rr, Nn, Nn, 0, RN, RN, pAl + 3 * 2048, pBe + 3 * 2048);

    // 5) S = Q^T K  M=4096, K=512
    mma_gemm<true, true, false><<<dim3(Nn / 128, Nn / 128, Bb), 512, SMEM_SZ>>>(
        pQ, pK, pS, Rr, Nn, Nn, Nn, RN, RN, NN, nullptr, nullptr);

    // 6) P = softmax rows of S
    softmax_kernel<<<Bb * Nn, 256>>>(pS);

    // 7) U = V @ P^T  M=512, K=4096
    mma_gemm<false, false, false><<<dim3(Nn / 128, Rr / 128, Bb), 512, SMEM_SZ>>>(
        pV, pS, pU, Nn, Nn, Nn, Nn, RN, NN, RN, nullptr, nullptr);

    // 8) U += F
    {
        int n4 = (int)(Bb * RN / 4);
        add_kernel<<<(n4 + 255) / 256, 256>>>(pU, pF, n4);
    }

    // 9) out = cbr(Wu @ (F+U))  M=2048, K=512
    mma_gemm<false, true, true><<<dim3(Nn / 128, Cc / 128, Bb), 512, SMEM_SZ>>>(
        Wl[4], pU, (float*)d_out, Rr, Rr, Nn, Nn, 0, RN, CN,
        pAl + 4 * 2048, pBe + 4 * 2048);
}

// round 6
// speedup vs baseline: 2.4875x; 2.1402x over previous
#include <cuda_runtime.h>
#include <cuda_bf16.h>
#include <cstdint>
#include <cstddef>

#define EPS_BN 1e-5f

constexpr int Bb = 4;
constexpr int Cc = 2048;
constexpr int Rr = 512;
constexpr int Nn = 4096;   // H*W

constexpr size_t NC = (size_t)Bb * Nn * Cc;   // 33.5M
constexpr size_t NR = (size_t)Bb * Nn * Rr;   // 8.39M
constexpr size_t NNe = (size_t)Bb * Nn * Nn;  // 67.1M

// W plane segment offsets (r,q,k,v,u) — host-side
constexpr size_t WOF[5] = {0, 1048576, 1310720, 1572864, 1835008};
constexpr size_t WTOT = 2883584;

// ---- scratch (allocation-free) ----
__device__ __nv_bfloat16 g_XTh[NC], g_XTl[NC];        // feature^T planes [B][N][C]
__device__ __nv_bfloat16 g_FTh[NR], g_FTl[NR];        // F^T planes [B][N][R]
__device__ float         g_FTf[NR];                   // F^T fp32
__device__ __nv_bfloat16 g_QTh[NR], g_QTl[NR];        // Q^T planes
__device__ __nv_bfloat16 g_KTh[NR], g_KTl[NR];        // K^T planes
__device__ __nv_bfloat16 g_Vh[NR],  g_Vl[NR];         // V planes [B][R][N]
__device__ float         g_S[NNe];                    // logits fp32
__device__ __nv_bfloat16 g_Ph[NNe], g_Pl[NNe];        // softmax planes [B][N][N]
__device__ float         g_UT[NR];                    // U^T fp32 [B][N][R]
__device__ __nv_bfloat16 g_WTh[NR], g_WTl[NR];        // (F+U)^T planes
__device__ __nv_bfloat16 g_Wph[WTOT], g_Wpl[WTOT];    // weight planes
__device__ float g_alpha[5 * 2048], g_beta[5 * 2048];

// ===================== helpers =====================
__device__ __forceinline__ uint32_t smem_u32(const void* p) {
    uint32_t a;
    asm("{ .reg .u64 t; cvta.to.shared.u64 t, %1; cvt.u32.u64 %0, t; }" : "=r"(a) : "l"(p));
    return a;
}
__device__ __forceinline__ void ldsm4(uint32_t* r, uint32_t addr) {
    asm volatile("ldmatrix.sync.aligned.m8n8.x4.shared.b16 {%0,%1,%2,%3}, [%4];"
                 : "=r"(r[0]), "=r"(r[1]), "=r"(r[2]), "=r"(r[3]) : "r"(addr));
}
__device__ __forceinline__ void mma_bf16(float* c, const uint32_t* a, uint32_t b0, uint32_t b1) {
    asm volatile(
        "mma.sync.aligned.m16n8k16.row.col.f32.bf16.bf16.f32 "
        "{%0,%1,%2,%3}, {%4,%5,%6,%7}, {%8,%9}, {%0,%1,%2,%3};"
        : "+f"(c[0]), "+f"(c[1]), "+f"(c[2]), "+f"(c[3])
        : "r"(a[0]), "r"(a[1]), "r"(a[2]), "r"(a[3]), "r"(b0), "r"(b1));
}
__device__ __forceinline__ void cp16(uint32_t s, const void* g) {
    asm volatile("cp.async.cg.shared.global [%0], [%1], 16;" :: "r"(s), "l"(g));
}
__device__ __forceinline__ void cp_commit() {
    asm volatile("cp.async.commit_group;" ::: "memory");
}
__device__ __forceinline__ void cp_wait0() {
    asm volatile("cp.async.wait_group 0;" ::: "memory");
}
__device__ __forceinline__ void split1(float x, __nv_bfloat16& h, __nv_bfloat16& l) {
    h = __float2bfloat16_rn(x);
    l = __float2bfloat16_rn(x - __bfloat162float(h));
}
__device__ __forceinline__ uint32_t pack2(__nv_bfloat16 a, __nv_bfloat16 b) {
    __nv_bfloat162 p; p.x = a; p.y = b;
    return *reinterpret_cast<uint32_t*>(&p);
}

// ===================== prep: BN fold + weight split (ONE launch) ============
struct PrepArgs {
    const float* W[5];
    const float* g[5];
    const float* b[5];
    const float* m[5];
    const float* v[5];
};

__global__ void prep_kernel(PrepArgs a) {
    const size_t wof[5] = {0, 1048576, 1310720, 1572864, 1835008};
    const int wsz[5] = {1048576, 262144, 262144, 262144, 1048576};
    int id = blockIdx.x * blockDim.x + threadIdx.x;
    if (id < 4096) {
        int L, i;
        if (id < 2048) { L = id >> 9; i = id & 511; }
        else { L = 4; i = id - 2048; }
        float al = a.g[L][i] * rsqrtf(a.v[L][i] + EPS_BN);
        g_alpha[L * 2048 + i] = al;
        g_beta[L * 2048 + i] = a.b[L][i] - a.m[L][i] * al;
        return;
    }
    size_t w = (size_t)id - 4096;
    if (w >= WTOT) return;
    int L = 0;
    size_t off = w;
    while (L < 4 && off >= (size_t)wsz[L]) { off -= wsz[L]; ++L; }
    float x = a.W[L][off];
    split1(x, g_Wph[wof[L] + off], g_Wpl[wof[L] + off]);
}

// ===================== feature transpose + split ============================
// feature [z][C][N] fp32 -> XT planes [z][N][C]
__global__ __launch_bounds__(256) void xt_kernel(const float* __restrict__ X) {
    __shared__ float s[32][33];
    const int c0 = blockIdx.x * 32;
    const int n0 = blockIdx.y * 32;
    const size_t zo = (size_t)blockIdx.z * Cc * Nn;
    const int tx = threadIdx.x & 31;
    const int ty = threadIdx.x >> 5;  // 0..7
#pragma unroll
    for (int i = 0; i < 4; ++i)
        s[ty + 8 * i][tx] = X[zo + (size_t)(c0 + ty + 8 * i) * Nn + n0 + tx];
    __syncthreads();
    const size_t zo2 = (size_t)blockIdx.z * Nn * Cc;
#pragma unroll
    for (int i = 0; i < 4; ++i) {
        float val = s[tx][ty + 8 * i];
        size_t o = zo2 + (size_t)(n0 + ty + 8 * i) * Cc + c0 + tx;
        split1(val, g_XTh[o], g_XTl[o]);
    }
}

// ===================== canonical split-bf16 GEMM ============================
// C[i,j] = sum_k A[i,k]*B[j,k];  A planes [M][K], B planes [N][K] (K contig).
// SCALE: 0 none, 1 row (alpha[i]), 2 col (alpha[j]); >0 implies ReLU.
// Block 128x128xBK32, 256 thr, 8 warps (warp tile 64x32), 2-stage cp.async.
constexpr int STG = 40960;         // bytes per stage: Ah,Al,Bh,Bl @ 10240 each
constexpr int GSM = 2 * STG;       // 80 KB dynamic smem

template <int SCALE, bool OF32, bool OPL>
__global__ __launch_bounds__(256, 2) void gemm_bf16s(
    const __nv_bfloat16* __restrict__ Ah, const __nv_bfloat16* __restrict__ Al,
    const __nv_bfloat16* __restrict__ Bh, const __nv_bfloat16* __restrict__ Bl,
    float* __restrict__ Cf, __nv_bfloat16* __restrict__ Ch, __nv_bfloat16* __restrict__ Cl,
    int K, int ldc, long sA, long sB, long sC,
    const float* __restrict__ alpha, const float* __restrict__ beta) {
    extern __shared__ __align__(16) char smem[];
    const uint32_t su = smem_u32(smem);

    const int t = threadIdx.x;
    const int lane = t & 31;
    const int wid = t >> 5;
    const int warp_m = wid >> 2;   // 0..1
    const int warp_n = wid & 3;    // 0..3
    const int bi = blockIdx.y * 128;
    const int bj = blockIdx.x * 128;
    const size_t zA = (size_t)sA * blockIdx.z;
    const size_t zB = (size_t)sB * blockIdx.z;
    const size_t zC = (size_t)sC * blockIdx.z;

    const int row = t >> 2;        // 0..63 base row (2 rows per thread via +64)
    const int kc = t & 3;          // 16B chunk within 64B k-row

    auto load_stage = [&](int stage, int k0) {
        const uint32_t sb = su + stage * STG;
#pragma unroll
        for (int i = 0; i < 2; ++i) {
            int r = row + 64 * i;
            const __nv_bfloat16* gah = Ah + zA + (size_t)(bi + r) * K + k0;
            const __nv_bfloat16* gal = Al + zA + (size_t)(bi + r) * K + k0;
            const __nv_bfloat16* gbh = Bh + zB + (size_t)(bj + r) * K + k0;
            const __nv_bfloat16* gbl = Bl + zB + (size_t)(bj + r) * K + k0;
            uint32_t so = r * 80 + kc * 16;
            cp16(sb + so,         (const char*)gah + kc * 16);
            cp16(sb + 10240 + so, (const char*)gal + kc * 16);
            cp16(sb + 20480 + so, (const char*)gbh + kc * 16);
            cp16(sb + 30720 + so, (const char*)gbl + kc * 16);
        }
        cp_commit();
    };

    float acc[4][4][4] = {};
    const int T = K / 32;

    load_stage(0, 0);

    const uint32_t aoff = (uint32_t)((warp_m * 64 + (lane & 15)) * 80 + (lane >> 4) * 16);
    const uint32_t boff = (uint32_t)(20480 + (warp_n * 32 + (lane & 15)) * 80 + (lane >> 4) * 16);

    for (int tt = 0; tt < T; ++tt) {
        cp_wait0();
        __syncthreads();
        if (tt + 1 < T) load_stage((tt + 1) & 1, (tt + 1) * 32);

        const uint32_t sb = su + (tt & 1) * STG;
        const uint32_t aHi = sb + aoff, aLo = aHi + 10240;
        const uint32_t bHi = sb + boff, bLo = bHi + 10240;

#pragma unroll
        for (int ks = 0; ks < 2; ++ks) {
            const uint32_t kof = (uint32_t)(ks * 32);
            uint32_t bh0[4], bh1[4], bl0[4], bl1[4];
            ldsm4(bh0, bHi + kof);
            ldsm4(bh1, bHi + 16 * 80 + kof);
            ldsm4(bl0, bLo + kof);
            ldsm4(bl1, bLo + 16 * 80 + kof);
#pragma unroll
            for (int mt = 0; mt < 4; ++mt) {
                uint32_t ah[4], al_[4];
                ldsm4(ah, aHi + (uint32_t)(mt * 16 * 80) + kof);
                ldsm4(al_, aLo + (uint32_t)(mt * 16 * 80) + kof);
#pragma unroll
                for (int nt = 0; nt < 4; ++nt) {
                    const uint32_t* bh = (nt >> 1) ? bh1 : bh0;
                    const uint32_t* bl = (nt >> 1) ? bl1 : bl0;
                    mma_bf16(acc[mt][nt], ah, bh[nt & 1], bh[2 + (nt & 1)]);
                    mma_bf16(acc[mt][nt], al_, bh[nt & 1], bh[2 + (nt & 1)]);
                    mma_bf16(acc[mt][nt], ah, bl[nt & 1], bl[2 + (nt & 1)]);
                }
            }
        }
        __syncthreads();
    }

    // ---- epilogue ----
#pragma unroll
    for (int mt = 0; mt < 4; ++mt) {
        const int m0 = bi + warp_m * 64 + mt * 16 + (lane >> 2);
        float ra0 = 1.f, rb0 = 0.f, ra1 = 1.f, rb1 = 0.f;
        if (SCALE == 1) {
            ra0 = alpha[m0]; rb0 = beta[m0];
            ra1 = alpha[m0 + 8]; rb1 = beta[m0 + 8];
        }
#pragma unroll
        for (int nt = 0; nt < 4; ++nt) {
            const int n = bj + warp_n * 32 + nt * 8 + (lane & 3) * 2;
            float v0 = acc[mt][nt][0], v1 = acc[mt][nt][1];
            float v2 = acc[mt][nt][2], v3 = acc[mt][nt][3];
            if (SCALE == 1) {
                v0 = fmaxf(fmaf(ra0, v0, rb0), 0.f); v1 = fmaxf(fmaf(ra0, v1, rb0), 0.f);
                v2 = fmaxf(fmaf(ra1, v2, rb1), 0.f); v3 = fmaxf(fmaf(ra1, v3, rb1), 0.f);
            } else if (SCALE == 2) {
                float ca0 = alpha[n], cb0 = beta[n], ca1 = alpha[n + 1], cb1 = beta[n + 1];
                v0 = fmaxf(fmaf(ca0, v0, cb0), 0.f); v1 = fmaxf(fmaf(ca1, v1, cb1), 0.f);
                v2 = fmaxf(fmaf(ca0, v2, cb0), 0.f); v3 = fmaxf(fmaf(ca1, v3, cb1), 0.f);
            }
            if (OF32) {
                *reinterpret_cast<float2*>(&Cf[zC + (size_t)m0 * ldc + n]) = make_float2(v0, v1);
                *reinterpret_cast<float2*>(&Cf[zC + (size_t)(m0 + 8) * ldc + n]) = make_float2(v2, v3);
            }
            if (OPL) {
                __nv_bfloat16 h0, l0, h1, l1;
                split1(v0, h0, l0); split1(v1, h1, l1);
                *reinterpret_cast<uint32_t*>(&Ch[zC + (size_t)m0 * ldc + n]) = pack2(h0, h1);
                *reinterpret_cast<uint32_t*>(&Cl[zC + (size_t)m0 * ldc + n]) = pack2(l0, l1);
                split1(v2, h0, l0); split1(v3, h1, l1);
                *reinterpret_cast<uint32_t*>(&Ch[zC + (size_t)(m0 + 8) * ldc + n]) = pack2(h0, h1);
                *reinterpret_cast<uint32_t*>(&Cl[zC + (size_t)(m0 + 8) * ldc + n]) = pack2(l0, l1);
            }
        }
    }
}

// ===================== softmax -> split planes ==============================
__global__ __launch_bounds__(256) void softmax_kernel() {
    const size_t ro = (size_t)blockIdx.x * Nn;
    const float* row = g_S + ro;
    const int t = threadIdx.x;
    __shared__ float redm[8], reds[8];

    float v[16];
    float m = -1e30f;
#pragma unroll
    for (int u = 0; u < 16; ++u) {
        v[u] = row[t + u * 256];
        m = fmaxf(m, v[u]);
    }
#pragma unroll
    for (int o = 16; o; o >>= 1) m = fmaxf(m, __shfl_xor_sync(0xffffffffu, m, o));
    if ((t & 31) == 0) redm[t >> 5] = m;
    __syncthreads();
    m = redm[0];
#pragma unroll
    for (int w = 1; w < 8; ++w) m = fmaxf(m, redm[w]);

    float s = 0.f;
#pragma unroll
    for (int u = 0; u < 16; ++u) {
        v[u] = __expf(v[u] - m);
        s += v[u];
    }
#pragma unroll
    for (int o = 16; o; o >>= 1) s += __shfl_xor_sync(0xffffffffu, s, o);
    if ((t & 31) == 0) reds[t >> 5] = s;
    __syncthreads();
    float tot = 0.f;
#pragma unroll
    for (int w = 0; w < 8; ++w) tot += reds[w];
    float inv = 1.0f / tot;
#pragma unroll
    for (int u = 0; u < 16; ++u) {
        float p = v[u] * inv;
        split1(p, g_Ph[ro + t + u * 256], g_Pl[ro + t + u * 256]);
    }
}

// ===================== add + split: WT = split(FTf + UT) ====================
__global__ void add_kernel() {
    size_t i = ((size_t)blockIdx.x * blockDim.x + threadIdx.x) * 4;
    if (i >= NR) return;
    float4 f = *reinterpret_cast<const float4*>(&g_FTf[i]);
    float4 u = *reinterpret_cast<const float4*>(&g_UT[i]);
    float w0 = f.x + u.x, w1 = f.y + u.y, w2 = f.z + u.z, w3 = f.w + u.w;
    __nv_bfloat16 h0, l0, h1, l1, h2, l2, h3, l3;
    split1(w0, h0, l0); split1(w1, h1, l1); split1(w2, h2, l2); split1(w3, h3, l3);
    uint2 hp, lp;
    hp.x = pack2(h0, h1); hp.y = pack2(h2, h3);
    lp.x = pack2(l0, l1); lp.y = pack2(l2, l3);
    *reinterpret_cast<uint2*>(&g_WTh[i]) = hp;
    *reinterpret_cast<uint2*>(&g_WTl[i]) = lp;
}

// ===================== host =====================
extern "C" void kernel_launch(void* const* d_in, const int* in_sizes, int n_in,
                              void* d_out, int out_size) {
    const float* feature = (const float*)d_in[0];
    PrepArgs pa;
    for (int L = 0; L < 5; ++L) {
        pa.W[L] = (const float*)d_in[1 + 5 * L + 0];
        pa.g[L] = (const float*)d_in[1 + 5 * L + 1];
        pa.b[L] = (const float*)d_in[1 + 5 * L + 2];
        pa.m[L] = (const float*)d_in[1 + 5 * L + 3];
        pa.v[L] = (const float*)d_in[1 + 5 * L + 4];
    }

    // symbol addresses
    __nv_bfloat16 *XTh, *XTl, *FTh, *FTl, *QTh, *QTl, *KTh, *KTl, *Vh, *Vl;
    __nv_bfloat16 *Ph, *Pl, *WTh, *WTl, *Wph, *Wpl;
    float *FTf, *S, *UT, *Al, *Be;
    cudaGetSymbolAddress((void**)&XTh, g_XTh); cudaGetSymbolAddress((void**)&XTl, g_XTl);
    cudaGetSymbolAddress((void**)&FTh, g_FTh); cudaGetSymbolAddress((void**)&FTl, g_FTl);
    cudaGetSymbolAddress((void**)&QTh, g_QTh); cudaGetSymbolAddress((void**)&QTl, g_QTl);
    cudaGetSymbolAddress((void**)&KTh, g_KTh); cudaGetSymbolAddress((void**)&KTl, g_KTl);
    cudaGetSymbolAddress((void**)&Vh, g_Vh);   cudaGetSymbolAddress((void**)&Vl, g_Vl);
    cudaGetSymbolAddress((void**)&Ph, g_Ph);   cudaGetSymbolAddress((void**)&Pl, g_Pl);
    cudaGetSymbolAddress((void**)&WTh, g_WTh); cudaGetSymbolAddress((void**)&WTl, g_WTl);
    cudaGetSymbolAddress((void**)&Wph, g_Wph); cudaGetSymbolAddress((void**)&Wpl, g_Wpl);
    cudaGetSymbolAddress((void**)&FTf, g_FTf); cudaGetSymbolAddress((void**)&S, g_S);
    cudaGetSymbolAddress((void**)&UT, g_UT);
    cudaGetSymbolAddress((void**)&Al, g_alpha); cudaGetSymbolAddress((void**)&Be, g_beta);

    cudaFuncSetAttribute(gemm_bf16s<2, true, true>,  cudaFuncAttributeMaxDynamicSharedMemorySize, GSM);
    cudaFuncSetAttribute(gemm_bf16s<2, false, true>, cudaFuncAttributeMaxDynamicSharedMemorySize, GSM);
    cudaFuncSetAttribute(gemm_bf16s<1, false, true>, cudaFuncAttributeMaxDynamicSharedMemorySize, GSM);
    cudaFuncSetAttribute(gemm_bf16s<0, true, false>, cudaFuncAttributeMaxDynamicSharedMemorySize, GSM);
    cudaFuncSetAttribute(gemm_bf16s<1, true, false>, cudaFuncAttributeMaxDynamicSharedMemorySize, GSM);

    const long sNR = (long)Nn * Rr;
    const long sNN = (long)Nn * Nn;

    // 0) prep (single launch)
    prep_kernel<<<(int)((WTOT + 4096 + 255) / 256), 256>>>(pa);

    // 1) XT = transpose+split(feature)
    xt_kernel<<<dim3(Cc / 32, Nn / 32, Bb), 256>>>(feature);

    // 2) FT = cbr-col(XT x Wr)   M=4096, N=512, K=2048  -> planes + fp32
    gemm_bf16s<2, true, true><<<dim3(4, 32, Bb), 256, GSM>>>(
        XTh, XTl, Wph + WOF[0], Wpl + WOF[0], FTf, FTh, FTl,
        Cc, Rr, (long)Nn * Cc, 0, sNR, Al + 0 * 2048, Be + 0 * 2048);

    // 3) QT = cbr-col(FT x Wq)   M=4096, N=512, K=512
    gemm_bf16s<2, false, true><<<dim3(4, 32, Bb), 256, GSM>>>(
        FTh, FTl, Wph + WOF[1], Wpl + WOF[1], nullptr, QTh, QTl,
        Rr, Rr, sNR, 0, sNR, Al + 1 * 2048, Be + 1 * 2048);

    // 4) KT = cbr-col(FT x Wk)
    gemm_bf16s<2, false, true><<<dim3(4, 32, Bb), 256, GSM>>>(
        FTh, FTl, Wph + WOF[2], Wpl + WOF[2], nullptr, KTh, KTl,
        Rr, Rr, sNR, 0, sNR, Al + 2 * 2048, Be + 2 * 2048);

    // 5) V = cbr-row(Wv x F) via A=Wv, B=FT   M=512, N=4096, K=512
    gemm_bf16s<1, false, true><<<dim3(32, 4, Bb), 256, GSM>>>(
        Wph + WOF[3], Wpl + WOF[3], FTh, FTl, nullptr, Vh, Vl,
        Rr, Nn, 0, sNR, (long)Rr * Nn, Al + 3 * 2048, Be + 3 * 2048);

    // 6) S = QT x KT^T   M=N=4096, K=512
    gemm_bf16s<0, true, false><<<dim3(32, 32, Bb), 256, GSM>>>(
        QTh, QTl, KTh, KTl, S, nullptr, nullptr,
        Rr, Nn, sNR, sNR, sNN, nullptr, nullptr);

    // 7) P = softmax rows -> split planes
    softmax_kernel<<<Bb * Nn, 256>>>();

    // 8) UT = P x V^T   M=4096, N=512, K=4096
    gemm_bf16s<0, true, false><<<dim3(4, 32, Bb), 256, GSM>>>(
        Ph, Pl, Vh, Vl, UT, nullptr, nullptr,
        Nn, Rr, sNN, (long)Rr * Nn, sNR, nullptr, nullptr);

    // 9) WT = split(FTf + UT)
    add_kernel<<<(int)((NR / 4 + 255) / 256), 256>>>();

    // 10) out = cbr-row(Wu x (F+U)) via A=Wu, B=WT   M=2048, N=4096, K=512
    gemm_bf16s<1, true, false><<<dim3(32, 16, Bb), 256, GSM>>>(
        Wph + WOF[4], Wpl + WOF[4], WTh, WTl, (float*)d_out, nullptr, nullptr,
        Rr, Nn, 0, sNR, (long)Cc * Nn, Al + 4 * 2048, Be + 4 * 2048);
}

// round 8
// speedup vs baseline: 2.4995x; 1.0048x over previous
#include <cuda_runtime.h>
#include <cuda_bf16.h>
#include <cstdint>
#include <cstddef>

#define EPS_BN 1e-5f

constexpr int Bb = 4;
constexpr int Cc = 2048;
constexpr int Rr = 512;
constexpr int Nn = 4096;   // H*W

constexpr size_t NC = (size_t)Bb * Nn * Cc;
constexpr size_t NR = (size_t)Bb * Nn * Rr;
constexpr size_t NNe = (size_t)Bb * Nn * Nn;

constexpr size_t WOF[5] = {0, 1048576, 1310720, 1572864, 1835008};
constexpr size_t WTOT = 2883584;

// ---- scratch (allocation-free) ----
__device__ __nv_bfloat16 g_XTh[NC], g_XTl[NC];
__device__ __nv_bfloat16 g_FTh[NR], g_FTl[NR];
__device__ float         g_FTf[NR];
__device__ __nv_bfloat16 g_QTh[NR], g_QTl[NR];
__device__ __nv_bfloat16 g_KTh[NR], g_KTl[NR];
__device__ __nv_bfloat16 g_Vh[NR], g_Vl[NR];
__device__ float         g_S[NNe];
__device__ __nv_bfloat16 g_Ph[NNe], g_Pl[NNe];
__device__ float         g_UT[NR];
__device__ __nv_bfloat16 g_WTh[NR], g_WTl[NR];
__device__ __nv_bfloat16 g_Wph[WTOT], g_Wpl[WTOT];
__device__ float g_alpha[5 * 2048], g_beta[5 * 2048];

// ===================== helpers =====================
__device__ __forceinline__ uint32_t smem_u32(const void* p) {
    uint32_t a;
    asm("{ .reg .u64 t; cvta.to.shared.u64 t, %1; cvt.u32.u64 %0, t; }" : "=r"(a) : "l"(p));
    return a;
}
__device__ __forceinline__ void ldsm4(uint32_t* r, uint32_t addr) {
    asm volatile("ldmatrix.sync.aligned.m8n8.x4.shared.b16 {%0,%1,%2,%3}, [%4];"
                 : "=r"(r[0]), "=r"(r[1]), "=r"(r[2]), "=r"(r[3]) : "r"(addr));
}
__device__ __forceinline__ void mma_bf16(float* c, const uint32_t* a, uint32_t b0, uint32_t b1) {
    asm volatile(
        "mma.sync.aligned.m16n8k16.row.col.f32.bf16.bf16.f32 "
        "{%0,%1,%2,%3}, {%4,%5,%6,%7}, {%8,%9}, {%0,%1,%2,%3};"
        : "+f"(c[0]), "+f"(c[1]), "+f"(c[2]), "+f"(c[3])
        : "r"(a[0]), "r"(a[1]), "r"(a[2]), "r"(a[3]), "r"(b0), "r"(b1));
}
__device__ __forceinline__ void cp16(uint32_t s, const void* g) {
    asm volatile("cp.async.cg.shared.global [%0], [%1], 16;" :: "r"(s), "l"(g));
}
__device__ __forceinline__ void cp_commit() {
    asm volatile("cp.async.commit_group;" ::: "memory");
}
__device__ __forceinline__ void cp_wait0() {
    asm volatile("cp.async.wait_group 0;" ::: "memory");
}
__device__ __forceinline__ void split1(float x, __nv_bfloat16& h, __nv_bfloat16& l) {
    h = __float2bfloat16_rn(x);
    l = __float2bfloat16_rn(x - __bfloat162float(h));
}
__device__ __forceinline__ uint32_t pack2(__nv_bfloat16 a, __nv_bfloat16 b) {
    __nv_bfloat162 p; p.x = a; p.y = b;
    return *reinterpret_cast<uint32_t*>(&p);
}

// ===================== prep =====================
struct PrepArgs {
    const float* W[5];
    const float* g[5];
    const float* b[5];
    const float* m[5];
    const float* v[5];
};

__global__ void prep_kernel(PrepArgs a) {
    const size_t wof[5] = {0, 1048576, 1310720, 1572864, 1835008};
    const int wsz[5] = {1048576, 262144, 262144, 262144, 1048576};
    int id = blockIdx.x * blockDim.x + threadIdx.x;
    if (id < 4096) {
        int L, i;
        if (id < 2048) { L = id >> 9; i = id & 511; }
        else { L = 4; i = id - 2048; }
        float al = a.g[L][i] * rsqrtf(a.v[L][i] + EPS_BN);
        g_alpha[L * 2048 + i] = al;
        g_beta[L * 2048 + i] = a.b[L][i] - a.m[L][i] * al;
        return;
    }
    size_t w = (size_t)id - 4096;
    if (w >= WTOT) return;
    int L = 0;
    size_t off = w;
    while (L < 4 && off >= (size_t)wsz[L]) { off -= wsz[L]; ++L; }
    float x = a.W[L][off];
    split1(x, g_Wph[wof[L] + off], g_Wpl[wof[L] + off]);
}

// ===================== feature transpose + split ============================
__global__ __launch_bounds__(256) void xt_kernel(const float* __restrict__ X) {
    __shared__ float s[32][33];
    const int c0 = blockIdx.x * 32;
    const int n0 = blockIdx.y * 32;
    const size_t zo = (size_t)blockIdx.z * Cc * Nn;
    const int tx = threadIdx.x & 31;
    const int ty = threadIdx.x >> 5;
#pragma unroll
    for (int i = 0; i < 4; ++i)
        s[ty + 8 * i][tx] = X[zo + (size_t)(c0 + ty + 8 * i) * Nn + n0 + tx];
    __syncthreads();
    const size_t zo2 = (size_t)blockIdx.z * Nn * Cc;
#pragma unroll
    for (int i = 0; i < 4; ++i) {
        float val = s[tx][ty + 8 * i];
        size_t o = zo2 + (size_t)(n0 + ty + 8 * i) * Cc + c0 + tx;
        split1(val, g_XTh[o], g_XTl[o]);
    }
}

// ===================== canonical split-bf16 GEMM ============================
// C[i,j] = sum_k A[i,k]*B[j,k];  A planes [M][K], B planes [N][K] (K contig).
// SCALE: 0 none, 1 row alpha[i], 2 col alpha[j]; >0 implies ReLU.
// Block tile 128x128xBK32, 128 threads (4 warps: 2m x 2n, warp tile 64x64),
// 2-stage cp.async, single barrier per k-tile.

template <int SCALE, bool OF32, bool OPL, bool WLO>
__global__ __launch_bounds__(128, 2) void gemm_bf16s(
    const __nv_bfloat16* __restrict__ Ah, const __nv_bfloat16* __restrict__ Al,
    const __nv_bfloat16* __restrict__ Bh, const __nv_bfloat16* __restrict__ Bl,
    float* __restrict__ Cf, __nv_bfloat16* __restrict__ Ch, __nv_bfloat16* __restrict__ Cl,
    int K, int ldc, long sA, long sB, long sC,
    const float* __restrict__ alpha, const float* __restrict__ beta) {
    extern __shared__ __align__(16) char smem[];
    const uint32_t su = smem_u32(smem);

    constexpr int STGB = 40960;     // Ah,Al,Bh,Bl @ 10240 each
    constexpr int BOFF = 20480;

    const int t = threadIdx.x;
    const int lane = t & 31;
    const int wid = t >> 5;
    const int warp_m = wid >> 1;    // 0..1
    const int warp_n = wid & 1;     // 0..1
    const int bi = blockIdx.y * 128;
    const int bj = blockIdx.x * 128;
    const size_t zA = (size_t)sA * blockIdx.z;
    const size_t zB = (size_t)sB * blockIdx.z;
    const size_t zC = (size_t)sC * blockIdx.z;

    const int row = t >> 2;         // 0..31 base row; +32*i covers 128
    const int kc = t & 3;

    auto load_stage = [&](int stage, int k0) {
        const uint32_t sb = su + stage * STGB;
#pragma unroll
        for (int i = 0; i < 4; ++i) {
            int r = row + 32 * i;
            uint32_t so = r * 80 + kc * 16;
            cp16(sb + so,         (const char*)(Ah + zA + (size_t)(bi + r) * K + k0) + kc * 16);
            cp16(sb + 10240 + so, (const char*)(Al + zA + (size_t)(bi + r) * K + k0) + kc * 16);
            cp16(sb + BOFF + so,  (const char*)(Bh + zB + (size_t)(bj + r) * K + k0) + kc * 16);
            cp16(sb + 30720 + so, (const char*)(Bl + zB + (size_t)(bj + r) * K + k0) + kc * 16);
        }
        cp_commit();
    };

    float acc[4][8][4] = {};    // mt x nt x frag
    const int T = K / 32;

    load_stage(0, 0);

    const uint32_t aoff = (uint32_t)((warp_m * 64 + (lane & 15)) * 80 + (lane >> 4) * 16);
    const uint32_t boff = (uint32_t)(BOFF + (warp_n * 64 + (lane & 15)) * 80 + (lane >> 4) * 16);

    for (int tt = 0; tt < T; ++tt) {
        cp_wait0();
        __syncthreads();
        if (tt + 1 < T) load_stage((tt + 1) & 1, (tt + 1) * 32);

        const uint32_t sb = su + (tt & 1) * STGB;
        const uint32_t aHi = sb + aoff, aLo = aHi + 10240;
        const uint32_t bHi = sb + boff, bLo = bHi + 10240;

#pragma unroll
        for (int ks = 0; ks < 2; ++ks) {
            const uint32_t kof = (uint32_t)(ks * 32);
            uint32_t bh[4][4], bl[4][4];
#pragma unroll
            for (int np = 0; np < 4; ++np) {
                ldsm4(bh[np], bHi + (uint32_t)(np * 16 * 80) + kof);
                ldsm4(bl[np], bLo + (uint32_t)(np * 16 * 80) + kof);
            }
#pragma unroll
            for (int mt = 0; mt < 4; ++mt) {
                uint32_t ah[4], al_[4];
                ldsm4(ah, aHi + (uint32_t)(mt * 16 * 80) + kof);
                ldsm4(al_, aLo + (uint32_t)(mt * 16 * 80) + kof);
#pragma unroll
                for (int nt = 0; nt < 8; ++nt) {
                    const uint32_t* h = bh[nt >> 1];
                    const uint32_t* l = bl[nt >> 1];
                    mma_bf16(acc[mt][nt], ah, h[nt & 1], h[2 + (nt & 1)]);
                    mma_bf16(acc[mt][nt], al_, h[nt & 1], h[2 + (nt & 1)]);
                    mma_bf16(acc[mt][nt], ah, l[nt & 1], l[2 + (nt & 1)]);
                }
            }
        }
    }

    // ---- epilogue ----
#pragma unroll
    for (int mt = 0; mt < 4; ++mt) {
        const int m0 = bi + warp_m * 64 + mt * 16 + (lane >> 2);
        float ra0 = 1.f, rb0 = 0.f, ra1 = 1.f, rb1 = 0.f;
        if (SCALE == 1) {
            ra0 = alpha[m0]; rb0 = beta[m0];
            ra1 = alpha[m0 + 8]; rb1 = beta[m0 + 8];
        }
#pragma unroll
        for (int nt = 0; nt < 8; ++nt) {
            const int n = bj + warp_n * 64 + nt * 8 + (lane & 3) * 2;
            float v0 = acc[mt][nt][0], v1 = acc[mt][nt][1];
            float v2 = acc[mt][nt][2], v3 = acc[mt][nt][3];
            if (SCALE == 1) {
                v0 = fmaxf(fmaf(ra0, v0, rb0), 0.f); v1 = fmaxf(fmaf(ra0, v1, rb0), 0.f);
                v2 = fmaxf(fmaf(ra1, v2, rb1), 0.f); v3 = fmaxf(fmaf(ra1, v3, rb1), 0.f);
            } else if (SCALE == 2) {
                float ca0 = alpha[n], cb0 = beta[n], ca1 = alpha[n + 1], cb1 = beta[n + 1];
                v0 = fmaxf(fmaf(ca0, v0, cb0), 0.f); v1 = fmaxf(fmaf(ca1, v1, cb1), 0.f);
                v2 = fmaxf(fmaf(ca0, v2, cb0), 0.f); v3 = fmaxf(fmaf(ca1, v3, cb1), 0.f);
            }
            if (OF32) {
                *reinterpret_cast<float2*>(&Cf[zC + (size_t)m0 * ldc + n]) = make_float2(v0, v1);
                *reinterpret_cast<float2*>(&Cf[zC + (size_t)(m0 + 8) * ldc + n]) = make_float2(v2, v3);
            }
            if (OPL) {
                __nv_bfloat16 h0, l0, h1, l1;
                split1(v0, h0, l0); split1(v1, h1, l1);
                *reinterpret_cast<uint32_t*>(&Ch[zC + (size_t)m0 * ldc + n]) = pack2(h0, h1);
                if (WLO) *reinterpret_cast<uint32_t*>(&Cl[zC + (size_t)m0 * ldc + n]) = pack2(l0, l1);
                split1(v2, h0, l0); split1(v3, h1, l1);
                *reinterpret_cast<uint32_t*>(&Ch[zC + (size_t)(m0 + 8) * ldc + n]) = pack2(h0, h1);
                if (WLO) *reinterpret_cast<uint32_t*>(&Cl[zC + (size_t)(m0 + 8) * ldc + n]) = pack2(l0, l1);
            }
        }
    }
}

// ===================== softmax -> split planes ==============================
__global__ __launch_bounds__(256) void softmax_kernel() {
    const size_t ro = (size_t)blockIdx.x * Nn;
    const float* row = g_S + ro;
    const int t = threadIdx.x;
    __shared__ float redm[8], reds[8];

    float v[16];
    float m = -1e30f;
#pragma unroll
    for (int u = 0; u < 16; ++u) {
        v[u] = row[t + u * 256];
        m = fmaxf(m, v[u]);
    }
#pragma unroll
    for (int o = 16; o; o >>= 1) m = fmaxf(m, __shfl_xor_sync(0xffffffffu, m, o));
    if ((t & 31) == 0) redm[t >> 5] = m;
    __syncthreads();
    m = redm[0];
#pragma unroll
    for (int w = 1; w < 8; ++w) m = fmaxf(m, redm[w]);

    float s = 0.f;
#pragma unroll
    for (int u = 0; u < 16; ++u) {
        v[u] = __expf(v[u] - m);
        s += v[u];
    }
#pragma unroll
    for (int o = 16; o; o >>= 1) s += __shfl_xor_sync(0xffffffffu, s, o);
    if ((t & 31) == 0) reds[t >> 5] = s;
    __syncthreads();
    float tot = 0.f;
#pragma unroll
    for (int w = 0; w < 8; ++w) tot += reds[w];
    float inv = 1.0f / tot;
#pragma unroll
    for (int u = 0; u < 16; ++u) {
        float p = v[u] * inv;
        split1(p, g_Ph[ro + t + u * 256], g_Pl[ro + t + u * 256]);
    }
}

// ===================== add + split ==========================================
__global__ void add_kernel() {
    size_t i = ((size_t)blockIdx.x * blockDim.x + threadIdx.x) * 4;
    if (i >= NR) return;
    float4 f = *reinterpret_cast<const float4*>(&g_FTf[i]);
    float4 u = *reinterpret_cast<const float4*>(&g_UT[i]);
    float w0 = f.x + u.x, w1 = f.y + u.y, w2 = f.z + u.z, w3 = f.w + u.w;
    __nv_bfloat16 h0, l0, h1, l1, h2, l2, h3, l3;
    split1(w0, h0, l0); split1(w1, h1, l1); split1(w2, h2, l2); split1(w3, h3, l3);
    uint2 hp, lp;
    hp.x = pack2(h0, h1); hp.y = pack2(h2, h3);
    lp.x = pack2(l0, l1); lp.y = pack2(l2, l3);
    *reinterpret_cast<uint2*>(&g_WTh[i]) = hp;
    *reinterpret_cast<uint2*>(&g_WTl[i]) = lp;
}

// ===================== host =====================
constexpr int GSM = 2 * 40960;

extern "C" void kernel_launch(void* const* d_in, const int* in_sizes, int n_in,
                              void* d_out, int out_size) {
    const float* feature = (const float*)d_in[0];
    PrepArgs pa;
    for (int L = 0; L < 5; ++L) {
        pa.W[L] = (const float*)d_in[1 + 5 * L + 0];
        pa.g[L] = (const float*)d_in[1 + 5 * L + 1];
        pa.b[L] = (const float*)d_in[1 + 5 * L + 2];
        pa.m[L] = (const float*)d_in[1 + 5 * L + 3];
        pa.v[L] = (const float*)d_in[1 + 5 * L + 4];
    }

    __nv_bfloat16 *XTh, *XTl, *FTh, *FTl, *QTh, *QTl, *KTh, *KTl, *Vh, *Vl;
    __nv_bfloat16 *Ph, *Pl, *WTh, *WTl, *Wph, *Wpl;
    float *FTf, *S, *UT, *Al, *Be;
    cudaGetSymbolAddress((void**)&XTh, g_XTh); cudaGetSymbolAddress((void**)&XTl, g_XTl);
    cudaGetSymbolAddress((void**)&FTh, g_FTh); cudaGetSymbolAddress((void**)&FTl, g_FTl);
    cudaGetSymbolAddress((void**)&QTh, g_QTh); cudaGetSymbolAddress((void**)&QTl, g_QTl);
    cudaGetSymbolAddress((void**)&KTh, g_KTh); cudaGetSymbolAddress((void**)&KTl, g_KTl);
    cudaGetSymbolAddress((void**)&Vh, g_Vh);   cudaGetSymbolAddress((void**)&Vl, g_Vl);
    cudaGetSymbolAddress((void**)&Ph, g_Ph);   cudaGetSymbolAddress((void**)&Pl, g_Pl);
    cudaGetSymbolAddress((void**)&WTh, g_WTh); cudaGetSymbolAddress((void**)&WTl, g_WTl);
    cudaGetSymbolAddress((void**)&Wph, g_Wph); cudaGetSymbolAddress((void**)&Wpl, g_Wpl);
    cudaGetSymbolAddress((void**)&FTf, g_FTf); cudaGetSymbolAddress((void**)&S, g_S);
    cudaGetSymbolAddress((void**)&UT, g_UT);
    cudaGetSymbolAddress((void**)&Al, g_alpha); cudaGetSymbolAddress((void**)&Be, g_beta);

    cudaFuncSetAttribute(gemm_bf16s<2, true, true, true>,   cudaFuncAttributeMaxDynamicSharedMemorySize, GSM);
    cudaFuncSetAttribute(gemm_bf16s<2, false, true, true>,  cudaFuncAttributeMaxDynamicSharedMemorySize, GSM);
    cudaFuncSetAttribute(gemm_bf16s<1, false, true, true>,  cudaFuncAttributeMaxDynamicSharedMemorySize, GSM);
    cudaFuncSetAttribute(gemm_bf16s<0, true, false, false>, cudaFuncAttributeMaxDynamicSharedMemorySize, GSM);
    cudaFuncSetAttribute(gemm_bf16s<1, true, false, false>, cudaFuncAttributeMaxDynamicSharedMemorySize, GSM);

    const long sNR = (long)Nn * Rr;
    const long sNN = (long)Nn * Nn;

    // 0) prep
    prep_kernel<<<(int)((WTOT + 4096 + 255) / 256), 256>>>(pa);

    // 1) XT = transpose+split(feature)
    xt_kernel<<<dim3(Cc / 32, Nn / 32, Bb), 256>>>(feature);

    // 2) FT = cbr-col(XT x Wr)   M=4096, N=512, K=2048
    gemm_bf16s<2, true, true, true><<<dim3(4, 32, Bb), 128, GSM>>>(
        XTh, XTl, Wph + WOF[0], Wpl + WOF[0], FTf, FTh, FTl,
        Cc, Rr, (long)Nn * Cc, 0, sNR, Al + 0 * 2048, Be + 0 * 2048);

    // 3) QT = cbr-col(FT x Wq)
    gemm_bf16s<2, false, true, true><<<dim3(4, 32, Bb), 128, GSM>>>(
        FTh, FTl, Wph + WOF[1], Wpl + WOF[1], nullptr, QTh, QTl,
        Rr, Rr, sNR, 0, sNR, Al + 1 * 2048, Be + 1 * 2048);

    // 4) KT = cbr-col(FT x Wk)
    gemm_bf16s<2, false, true, true><<<dim3(4, 32, Bb), 128, GSM>>>(
        FTh, FTl, Wph + WOF[2], Wpl + WOF[2], nullptr, KTh, KTl,
        Rr, Rr, sNR, 0, sNR, Al + 2 * 2048, Be + 2 * 2048);

    // 5) V = cbr-row(Wv x F)   M=512, N=4096, K=512 (split planes)
    gemm_bf16s<1, false, true, true><<<dim3(32, 4, Bb), 128, GSM>>>(
        Wph + WOF[3], Wpl + WOF[3], FTh, FTl, nullptr, Vh, Vl,
        Rr, Nn, 0, sNR, (long)Rr * Nn, Al + 3 * 2048, Be + 3 * 2048);

    // 6) S = QT x KT^T   M=N=4096, K=512
    gemm_bf16s<0, true, false, false><<<dim3(32, 32, Bb), 128, GSM>>>(
        QTh, QTl, KTh, KTl, S, nullptr, nullptr,
        Rr, Nn, sNR, sNR, sNN, nullptr, nullptr);

    // 7) P = softmax rows -> split planes
    softmax_kernel<<<Bb * Nn, 256>>>();

    // 8) UT = P x V^T   M=4096, N=512, K=4096 (full split)
    gemm_bf16s<0, true, false, false><<<dim3(4, 32, Bb), 128, GSM>>>(
        Ph, Pl, Vh, Vl, UT, nullptr, nullptr,
        Nn, Rr, sNN, (long)Rr * Nn, sNR, nullptr, nullptr);

    // 9) WT = split(FTf + UT)
    add_kernel<<<(int)((NR / 4 + 255) / 256), 256>>>();

    // 10) out = cbr-row(Wu x (F+U))   M=2048, N=4096, K=512
    gemm_bf16s<1, true, false, false><<<dim3(32, 16, Bb), 128, GSM>>>(
        Wph + WOF[4], Wpl + WOF[4], WTh, WTl, (float*)d_out, nullptr, nullptr,
        Rr, Nn, 0, sNR, (long)Cc * Nn, Al + 4 * 2048, Be + 4 * 2048);
}